// round 1
// baseline (speedup 1.0000x reference)
#include <cuda_runtime.h>
#include <math.h>

// ---------------------------------------------------------------------------
// MultiHeadAttention: B=2, S=2048, D=1024, H=16, DK=64
// Outputs: out (B,S,D) fp32  then  attn (B,H,S,S) fp32 (packing detected via out_size)
// ---------------------------------------------------------------------------

#define DMODEL 1024
#define NHEAD  16
#define DK     64
#define BATCH  2
#define SEQ    2048
#define MTOT   (BATCH * SEQ)                 /* 4096 */
#define OUT_ELEMS   ((long long)MTOT * DMODEL)              /* 4,194,304   */
#define ATTN_ELEMS  ((long long)BATCH * NHEAD * SEQ * SEQ)  /* 134,217,728 */

// Scratch (allocation-free rule: __device__ globals)
__device__ float g_Q[MTOT * DMODEL];
__device__ float g_K[MTOT * DMODEL];
__device__ float g_V[MTOT * DMODEL];
__device__ float g_ctx[MTOT * DMODEL];
__device__ float g_Wt[4 * DMODEL * DMODEL];          // transposed weights
__device__ float g_attn[134217728];                  // used only if attn not in d_out
__device__ float g_outscratch[MTOT * DMODEL];        // used only if out not in d_out

// ---------------------------------------------------------------------------
// Weight transpose: dst[k][n] = src[n][k]  (1024x1024)
// ---------------------------------------------------------------------------
__global__ void transpose_k(const float* __restrict__ src, float* __restrict__ dst) {
    __shared__ float t[32][33];
    int bx = blockIdx.x * 32, by = blockIdx.y * 32;
    int x = bx + threadIdx.x;
#pragma unroll
    for (int i = 0; i < 32; i += 8)
        t[threadIdx.y + i][threadIdx.x] = src[(size_t)(by + threadIdx.y + i) * DMODEL + x];
    __syncthreads();
    int x2 = by + threadIdx.x;
#pragma unroll
    for (int i = 0; i < 32; i += 8)
        dst[(size_t)(bx + threadIdx.y + i) * DMODEL + x2] = t[threadIdx.x][threadIdx.y + i];
}

// ---------------------------------------------------------------------------
// SGEMM:  C[4096,1024] = A[4096,1024] @ Bt[1024,1024] + bias
// 128x128 tile, BK=16, 8x8 per thread, 256 threads
// ---------------------------------------------------------------------------
__global__ void __launch_bounds__(256) sgemm_bias_k(
    const float* __restrict__ A, const float* __restrict__ Bt,
    const float* __restrict__ bias, float* __restrict__ C)
{
    constexpr int BM = 128, BN = 128, BK = 16, N = 1024, K = 1024;
    __shared__ float As[BK][BM];
    __shared__ float Bs[BK][BN];
    const int tid = threadIdx.x;
    const int tx = tid & 15, ty = tid >> 4;
    const int m0 = blockIdx.y * BM, n0 = blockIdx.x * BN;
    const int aRow = tid >> 2, aCol = (tid & 3) << 2;    // A tile: 64 rows/pass x 16 cols
    const int bRow = tid >> 5, bCol = (tid & 31) << 2;   // B tile: 8 rows/pass x 128 cols
    float acc[8][8] = {};

    for (int k0 = 0; k0 < K; k0 += BK) {
#pragma unroll
        for (int r = 0; r < BM; r += 64) {
            float4 v = *(const float4*)&A[(size_t)(m0 + aRow + r) * K + k0 + aCol];
            As[aCol + 0][aRow + r] = v.x;
            As[aCol + 1][aRow + r] = v.y;
            As[aCol + 2][aRow + r] = v.z;
            As[aCol + 3][aRow + r] = v.w;
        }
#pragma unroll
        for (int r = 0; r < BK; r += 8)
            *(float4*)&Bs[bRow + r][bCol] =
                *(const float4*)&Bt[(size_t)(k0 + bRow + r) * N + n0 + bCol];
        __syncthreads();
#pragma unroll
        for (int kk = 0; kk < BK; kk++) {
            float4 a0 = *(const float4*)&As[kk][ty * 8];
            float4 a1 = *(const float4*)&As[kk][ty * 8 + 4];
            float4 b0 = *(const float4*)&Bs[kk][tx * 8];
            float4 b1 = *(const float4*)&Bs[kk][tx * 8 + 4];
            float ra[8] = {a0.x, a0.y, a0.z, a0.w, a1.x, a1.y, a1.z, a1.w};
            float rb[8] = {b0.x, b0.y, b0.z, b0.w, b1.x, b1.y, b1.z, b1.w};
#pragma unroll
            for (int i = 0; i < 8; i++)
#pragma unroll
                for (int j = 0; j < 8; j++)
                    acc[i][j] += ra[i] * rb[j];
        }
        __syncthreads();
    }
    float bv[8];
#pragma unroll
    for (int j = 0; j < 8; j++) bv[j] = bias[n0 + tx * 8 + j];
#pragma unroll
    for (int i = 0; i < 8; i++) {
        float4 o0 = {acc[i][0] + bv[0], acc[i][1] + bv[1], acc[i][2] + bv[2], acc[i][3] + bv[3]};
        float4 o1 = {acc[i][4] + bv[4], acc[i][5] + bv[5], acc[i][6] + bv[6], acc[i][7] + bv[7]};
        float* cp = &C[(size_t)(m0 + ty * 8 + i) * N + n0 + tx * 8];
        *(float4*)cp = o0;
        *(float4*)(cp + 4) = o1;
    }
}

// ---------------------------------------------------------------------------
// Scores:  attn[bh, m, n] = (Q_h[m,:] . K_h[n,:]) * 0.125, masked
// 128x128 tile per CTA over (Sq, Sk); K-depth 64 in two BK=32 chunks
// ---------------------------------------------------------------------------
__global__ void __launch_bounds__(256) scores_k(float* __restrict__ attn,
                                               const int* __restrict__ mask)
{
    constexpr int BM = 128, BK = 32;
    __shared__ float Qs[BK][BM];
    __shared__ float Ks[BK][BM];
    const int bh = blockIdx.z, b = bh >> 4, h = bh & 15;
    const float* qb = g_Q + (size_t)b * SEQ * DMODEL + h * DK;
    const float* kb = g_K + (size_t)b * SEQ * DMODEL + h * DK;
    const int m0 = blockIdx.y * BM, n0 = blockIdx.x * BM;
    const int tid = threadIdx.x, tx = tid & 15, ty = tid >> 4;
    const int lRow = tid >> 3, lCol = (tid & 7) << 2;    // 32 rows/pass x 32 cols
    float acc[8][8] = {};

    for (int k0 = 0; k0 < DK; k0 += BK) {
#pragma unroll
        for (int r = 0; r < BM; r += 32) {
            float4 v = *(const float4*)&qb[(size_t)(m0 + lRow + r) * DMODEL + k0 + lCol];
            Qs[lCol + 0][lRow + r] = v.x;
            Qs[lCol + 1][lRow + r] = v.y;
            Qs[lCol + 2][lRow + r] = v.z;
            Qs[lCol + 3][lRow + r] = v.w;
            float4 w = *(const float4*)&kb[(size_t)(n0 + lRow + r) * DMODEL + k0 + lCol];
            Ks[lCol + 0][lRow + r] = w.x;
            Ks[lCol + 1][lRow + r] = w.y;
            Ks[lCol + 2][lRow + r] = w.z;
            Ks[lCol + 3][lRow + r] = w.w;
        }
        __syncthreads();
#pragma unroll
        for (int kk = 0; kk < BK; kk++) {
            float4 a0 = *(const float4*)&Qs[kk][ty * 8];
            float4 a1 = *(const float4*)&Qs[kk][ty * 8 + 4];
            float4 b0 = *(const float4*)&Ks[kk][tx * 8];
            float4 b1 = *(const float4*)&Ks[kk][tx * 8 + 4];
            float ra[8] = {a0.x, a0.y, a0.z, a0.w, a1.x, a1.y, a1.z, a1.w};
            float rb[8] = {b0.x, b0.y, b0.z, b0.w, b1.x, b1.y, b1.z, b1.w};
#pragma unroll
            for (int i = 0; i < 8; i++)
#pragma unroll
                for (int j = 0; j < 8; j++)
                    acc[i][j] += ra[i] * rb[j];
        }
        __syncthreads();
    }
    const float scale = 0.125f;
    int mk[8];
#pragma unroll
    for (int j = 0; j < 8; j++) mk[j] = mask[b * SEQ + n0 + tx * 8 + j];
#pragma unroll
    for (int i = 0; i < 8; i++) {
        float v[8];
#pragma unroll
        for (int j = 0; j < 8; j++) {
            v[j] = acc[i][j] * scale;
            if (mk[j] == 0) v[j] = -1e9f;
        }
        float* op = attn + ((size_t)bh * SEQ + m0 + ty * 8 + i) * SEQ + n0 + tx * 8;
        *(float4*)op = make_float4(v[0], v[1], v[2], v[3]);
        *(float4*)(op + 4) = make_float4(v[4], v[5], v[6], v[7]);
    }
}

// ---------------------------------------------------------------------------
// Row softmax over 2048 elems, one CTA per row, regs-resident (1 read + 1 write)
// ---------------------------------------------------------------------------
__global__ void __launch_bounds__(256) softmax_k(float* __restrict__ attn)
{
    float* p = attn + (size_t)blockIdx.x * SEQ;
    const int tid = threadIdx.x;
    __shared__ float red[256];
    float v[8];
    float mx = -INFINITY;
#pragma unroll
    for (int i = 0; i < 8; i++) {
        v[i] = p[tid + i * 256];
        mx = fmaxf(mx, v[i]);
    }
    red[tid] = mx;
    __syncthreads();
#pragma unroll
    for (int s = 128; s > 0; s >>= 1) {
        if (tid < s) red[tid] = fmaxf(red[tid], red[tid + s]);
        __syncthreads();
    }
    mx = red[0];
    __syncthreads();
    float sum = 0.f;
#pragma unroll
    for (int i = 0; i < 8; i++) {
        v[i] = __expf(v[i] - mx);
        sum += v[i];
    }
    red[tid] = sum;
    __syncthreads();
#pragma unroll
    for (int s = 128; s > 0; s >>= 1) {
        if (tid < s) red[tid] += red[tid + s];
        __syncthreads();
    }
    float inv = 1.0f / red[0];
#pragma unroll
    for (int i = 0; i < 8; i++) p[tid + i * 256] = v[i] * inv;
}

// ---------------------------------------------------------------------------
// ctx = attn @ V_h   per (b,h): M=2048, N=64, K=2048; BM=128, BN=64, BK=32
// ---------------------------------------------------------------------------
__global__ void __launch_bounds__(256) av_k(const float* __restrict__ attn)
{
    constexpr int BM = 128, BN = 64, BK = 32;
    __shared__ float As[BK][BM];
    __shared__ float Bs[BK][BN];
    const int bh = blockIdx.y, b = bh >> 4, h = bh & 15;
    const int m0 = blockIdx.x * BM;
    const float* arow = attn + ((size_t)bh * SEQ + m0) * SEQ;
    const float* vb = g_V + (size_t)b * SEQ * DMODEL + h * DK;
    const int tid = threadIdx.x, tx = tid & 15, ty = tid >> 4;
    const int aRow = tid >> 3, aCol = (tid & 7) << 2;     // 32 rows/pass, 4 passes
    const int bRow = tid >> 4, bCol = (tid & 15) << 2;    // 16 rows/pass, 2 passes
    float acc[8][4] = {};

    for (int k0 = 0; k0 < SEQ; k0 += BK) {
#pragma unroll
        for (int r = 0; r < BM; r += 32) {
            float4 v = *(const float4*)&arow[(size_t)(aRow + r) * SEQ + k0 + aCol];
            As[aCol + 0][aRow + r] = v.x;
            As[aCol + 1][aRow + r] = v.y;
            As[aCol + 2][aRow + r] = v.z;
            As[aCol + 3][aRow + r] = v.w;
        }
#pragma unroll
        for (int r = 0; r < BK; r += 16)
            *(float4*)&Bs[bRow + r][bCol] =
                *(const float4*)&vb[(size_t)(k0 + bRow + r) * DMODEL + bCol];
        __syncthreads();
#pragma unroll
        for (int kk = 0; kk < BK; kk++) {
            float4 a0 = *(const float4*)&As[kk][ty * 8];
            float4 a1 = *(const float4*)&As[kk][ty * 8 + 4];
            float4 b0 = *(const float4*)&Bs[kk][tx * 4];
            float ra[8] = {a0.x, a0.y, a0.z, a0.w, a1.x, a1.y, a1.z, a1.w};
            float rb[4] = {b0.x, b0.y, b0.z, b0.w};
#pragma unroll
            for (int i = 0; i < 8; i++)
#pragma unroll
                for (int j = 0; j < 4; j++)
                    acc[i][j] += ra[i] * rb[j];
        }
        __syncthreads();
    }
#pragma unroll
    for (int i = 0; i < 8; i++) {
        float* cp = &g_ctx[(size_t)(b * SEQ + m0 + ty * 8 + i) * DMODEL + h * DK + tx * 4];
        *(float4*)cp = make_float4(acc[i][0], acc[i][1], acc[i][2], acc[i][3]);
    }
}

// ---------------------------------------------------------------------------
extern "C" void kernel_launch(void* const* d_in, const int* in_sizes, int n_in,
                              void* d_out, int out_size)
{
    const float* query = (const float*)d_in[0];
    const float* key_i = (const float*)d_in[1];
    const float* value = (const float*)d_in[2];
    const int*   mask  = (const int*)d_in[3];
    const float* w_q = (const float*)d_in[4];
    const float* b_q = (const float*)d_in[5];
    const float* w_k = (const float*)d_in[6];
    const float* b_k = (const float*)d_in[7];
    const float* w_v = (const float*)d_in[8];
    const float* b_v = (const float*)d_in[9];
    const float* w_o = (const float*)d_in[10];
    const float* b_o = (const float*)d_in[11];

    float *pQ, *pK, *pV, *pCtx, *pWt, *pAttn, *pOutS;
    cudaGetSymbolAddress((void**)&pQ, g_Q);
    cudaGetSymbolAddress((void**)&pK, g_K);
    cudaGetSymbolAddress((void**)&pV, g_V);
    cudaGetSymbolAddress((void**)&pCtx, g_ctx);
    cudaGetSymbolAddress((void**)&pWt, g_Wt);
    cudaGetSymbolAddress((void**)&pAttn, g_attn);
    cudaGetSymbolAddress((void**)&pOutS, g_outscratch);

    // Output packing: reference returns (out, attn). Detect what d_out holds.
    float* outp = (float*)d_out;
    float* attnp;
    long long osz = (long long)out_size;
    if (osz >= OUT_ELEMS + ATTN_ELEMS) {
        attnp = (float*)d_out + OUT_ELEMS;          // both outputs, out first
    } else if (osz == ATTN_ELEMS) {
        attnp = (float*)d_out;                      // attn only
        outp = pOutS;
    } else {
        attnp = pAttn;                              // out only
    }

    const int W = DMODEL * DMODEL;
    dim3 tb(32, 8);
    transpose_k<<<dim3(32, 32), tb>>>(w_q, pWt + 0 * W);
    transpose_k<<<dim3(32, 32), tb>>>(w_k, pWt + 1 * W);
    transpose_k<<<dim3(32, 32), tb>>>(w_v, pWt + 2 * W);
    transpose_k<<<dim3(32, 32), tb>>>(w_o, pWt + 3 * W);

    sgemm_bias_k<<<dim3(8, 32), 256>>>(query, pWt + 0 * W, b_q, pQ);
    sgemm_bias_k<<<dim3(8, 32), 256>>>(key_i, pWt + 1 * W, b_k, pK);
    sgemm_bias_k<<<dim3(8, 32), 256>>>(value, pWt + 2 * W, b_v, pV);

    scores_k<<<dim3(16, 16, BATCH * NHEAD), 256>>>(attnp, mask);
    softmax_k<<<dim3(BATCH * NHEAD * SEQ), 256>>>(attnp);
    av_k<<<dim3(16, BATCH * NHEAD), 256>>>(attnp);

    sgemm_bias_k<<<dim3(8, 32), 256>>>(pCtx, pWt + 3 * W, b_o, outp);
}

// round 2
// speedup vs baseline: 2.3991x; 2.3991x over previous
#include <cuda_runtime.h>
#include <math.h>
#include <stdint.h>

// ---------------------------------------------------------------------------
// MultiHeadAttention: B=2, S=2048, D=1024, H=16, DK=64  — tf32 mma.sync version
// ---------------------------------------------------------------------------

#define DMODEL 1024
#define NHEAD  16
#define DK     64
#define BATCH  2
#define SEQ    2048
#define MTOT   (BATCH * SEQ)
#define OUT_ELEMS   ((long long)MTOT * DMODEL)
#define ATTN_ELEMS  ((long long)BATCH * NHEAD * SEQ * SEQ)

__device__ float g_Q[MTOT * DMODEL];
__device__ float g_K[MTOT * DMODEL];
__device__ float g_V[MTOT * DMODEL];
__device__ float g_ctx[MTOT * DMODEL];
__device__ float g_Wt[4 * DMODEL * DMODEL];
__device__ float g_attn[134217728];
__device__ float g_outscratch[MTOT * DMODEL];

// ---------------------------------------------------------------------------
__device__ __forceinline__ uint32_t f2tf(float x) {
    uint32_t r;
    asm("cvt.rna.tf32.f32 %0, %1;" : "=r"(r) : "f"(x));
    return r;
}

__device__ __forceinline__ void mma_tf32(float c[4], const uint32_t a[4], const uint32_t b[2]) {
    asm volatile(
        "mma.sync.aligned.m16n8k8.row.col.f32.tf32.tf32.f32 "
        "{%0,%1,%2,%3},{%4,%5,%6,%7},{%8,%9},{%0,%1,%2,%3};"
        : "+f"(c[0]), "+f"(c[1]), "+f"(c[2]), "+f"(c[3])
        : "r"(a[0]), "r"(a[1]), "r"(a[2]), "r"(a[3]), "r"(b[0]), "r"(b[1]));
}

// ---------------------------------------------------------------------------
// Weight transpose 1024x1024
// ---------------------------------------------------------------------------
__global__ void transpose_k(const float* __restrict__ src, float* __restrict__ dst) {
    __shared__ float t[32][33];
    int bx = blockIdx.x * 32, by = blockIdx.y * 32;
    int x = bx + threadIdx.x;
#pragma unroll
    for (int i = 0; i < 32; i += 8)
        t[threadIdx.y + i][threadIdx.x] = src[(size_t)(by + threadIdx.y + i) * DMODEL + x];
    __syncthreads();
    int x2 = by + threadIdx.x;
#pragma unroll
    for (int i = 0; i < 32; i += 8)
        dst[(size_t)(bx + threadIdx.y + i) * DMODEL + x2] = t[threadIdx.x][threadIdx.y + i];
}

// ---------------------------------------------------------------------------
// tf32 GEMM:  C[4096,1024] = A[4096,1024] @ Bt[1024,1024] + bias
// BM=128 BN=128 BK=32; 8 warps, warp tile 64x32 (mtiles=4, ntiles=4)
// As[m][k] stride 36 (=4 mod 32), Bs[k][n] stride 136 (=8 mod 32)
// ---------------------------------------------------------------------------
__global__ void __launch_bounds__(256) sgemm_tf32_k(
    const float* __restrict__ A, const float* __restrict__ Bt,
    const float* __restrict__ bias, float* __restrict__ C)
{
    constexpr int BM = 128, BN = 128, BK = 32, LDA = BK + 4, LDB = BN + 8;
    constexpr int K = 1024, N = 1024;
    __shared__ uint32_t As[BM * LDA];
    __shared__ uint32_t Bs[BK * LDB];
    const int tid = threadIdx.x, lane = tid & 31, wid = tid >> 5;
    const int wm = (wid & 1) * 64, wn = (wid >> 1) * 32;
    const int g = lane >> 2, tg = lane & 3;
    const int m0 = blockIdx.y * BM, n0 = blockIdx.x * BN;
    const int aRow = tid >> 3, aCol = (tid & 7) * 4;
    const int bRow = tid >> 5, bCol = (tid & 31) * 4;

    float4 pa[4], pb[4];
#pragma unroll
    for (int r = 0; r < 4; r++) {
        pa[r] = *(const float4*)&A[(size_t)(m0 + aRow + r * 32) * K + aCol];
        pb[r] = *(const float4*)&Bt[(size_t)(bRow + r * 8) * N + n0 + bCol];
    }

    float acc[4][4][4] = {};

    for (int k0 = 0; k0 < K; k0 += BK) {
#pragma unroll
        for (int r = 0; r < 4; r++) {
            uint4 va = {f2tf(pa[r].x), f2tf(pa[r].y), f2tf(pa[r].z), f2tf(pa[r].w)};
            *(uint4*)&As[(aRow + r * 32) * LDA + aCol] = va;
            uint4 vb = {f2tf(pb[r].x), f2tf(pb[r].y), f2tf(pb[r].z), f2tf(pb[r].w)};
            *(uint4*)&Bs[(bRow + r * 8) * LDB + bCol] = vb;
        }
        __syncthreads();
        if (k0 + BK < K) {
#pragma unroll
            for (int r = 0; r < 4; r++) {
                pa[r] = *(const float4*)&A[(size_t)(m0 + aRow + r * 32) * K + k0 + BK + aCol];
                pb[r] = *(const float4*)&Bt[(size_t)(k0 + BK + bRow + r * 8) * N + n0 + bCol];
            }
        }
#pragma unroll
        for (int ks = 0; ks < 4; ks++) {
            uint32_t af[4][4], bf[4][2];
#pragma unroll
            for (int mt = 0; mt < 4; mt++) {
                int mb = wm + mt * 16;
                af[mt][0] = As[(mb + g) * LDA + ks * 8 + tg];
                af[mt][1] = As[(mb + g + 8) * LDA + ks * 8 + tg];
                af[mt][2] = As[(mb + g) * LDA + ks * 8 + tg + 4];
                af[mt][3] = As[(mb + g + 8) * LDA + ks * 8 + tg + 4];
            }
#pragma unroll
            for (int nt = 0; nt < 4; nt++) {
                int col = wn + nt * 8 + g;
                bf[nt][0] = Bs[(ks * 8 + tg) * LDB + col];
                bf[nt][1] = Bs[(ks * 8 + tg + 4) * LDB + col];
            }
#pragma unroll
            for (int mt = 0; mt < 4; mt++)
#pragma unroll
                for (int nt = 0; nt < 4; nt++)
                    mma_tf32(acc[mt][nt], af[mt], bf[nt]);
        }
        __syncthreads();
    }

#pragma unroll
    for (int mt = 0; mt < 4; mt++) {
        int r0 = m0 + wm + mt * 16 + g;
#pragma unroll
        for (int nt = 0; nt < 4; nt++) {
            int col = n0 + wn + nt * 8 + 2 * tg;
            float b0 = bias[col], b1 = bias[col + 1];
            *(float2*)&C[(size_t)r0 * N + col] =
                make_float2(acc[mt][nt][0] + b0, acc[mt][nt][1] + b1);
            *(float2*)&C[(size_t)(r0 + 8) * N + col] =
                make_float2(acc[mt][nt][2] + b0, acc[mt][nt][3] + b1);
        }
    }
}

// ---------------------------------------------------------------------------
// Scores (tf32): attn[bh,m,n] = (Q_h[m,:].K_h[n,:]) * 0.125, masked
// BM=BN=128, K-depth 64 in two BK=32 tiles
// ---------------------------------------------------------------------------
__global__ void __launch_bounds__(256) scores_tf32_k(float* __restrict__ attn,
                                                    const int* __restrict__ mask)
{
    constexpr int BM = 128, BK = 32, LDA = BK + 4, LDB = BM + 8;
    __shared__ uint32_t As[BM * LDA];   // Q [m][k]
    __shared__ uint32_t Bs[BK * LDB];   // K^T [k][n]
    const int bh = blockIdx.z, b = bh >> 4, h = bh & 15;
    const float* qb = g_Q + (size_t)b * SEQ * DMODEL + h * DK;
    const float* kb = g_K + (size_t)b * SEQ * DMODEL + h * DK;
    const int tid = threadIdx.x, lane = tid & 31, wid = tid >> 5;
    const int wm = (wid & 1) * 64, wn = (wid >> 1) * 32;
    const int g = lane >> 2, tg = lane & 3;
    const int m0 = blockIdx.y * BM, n0 = blockIdx.x * BM;
    const int aRow = tid >> 3, aCol = (tid & 7) * 4;
    const int kN = tid >> 3, kK = (tid & 7) * 4;   // K-matrix loader: n=kN(+32r), k=kK

    float4 pa[4], pb[4];
#pragma unroll
    for (int r = 0; r < 4; r++) {
        pa[r] = *(const float4*)&qb[(size_t)(m0 + aRow + r * 32) * DMODEL + kK ? 0 : 0, // placeholder avoided below
                 (size_t)(m0 + aRow + r * 32) * DMODEL + aCol];
        pb[r] = *(const float4*)&kb[(size_t)(n0 + kN + r * 32) * DMODEL + kK];
    }

    float acc[4][4][4] = {};

    for (int k0 = 0; k0 < DK; k0 += BK) {
#pragma unroll
        for (int r = 0; r < 4; r++) {
            uint4 va = {f2tf(pa[r].x), f2tf(pa[r].y), f2tf(pa[r].z), f2tf(pa[r].w)};
            *(uint4*)&As[(aRow + r * 32) * LDA + aCol] = va;
            // scatter K[n][k] -> Bs[k][n]
            int n = kN + r * 32;
            Bs[(kK + 0) * LDB + n] = f2tf(pb[r].x);
            Bs[(kK + 1) * LDB + n] = f2tf(pb[r].y);
            Bs[(kK + 2) * LDB + n] = f2tf(pb[r].z);
            Bs[(kK + 3) * LDB + n] = f2tf(pb[r].w);
        }
        __syncthreads();
        if (k0 + BK < DK) {
#pragma unroll
            for (int r = 0; r < 4; r++) {
                pa[r] = *(const float4*)&qb[(size_t)(m0 + aRow + r * 32) * DMODEL + k0 + BK + aCol];
                pb[r] = *(const float4*)&kb[(size_t)(n0 + kN + r * 32) * DMODEL + k0 + BK + kK];
            }
        }
#pragma unroll
        for (int ks = 0; ks < 4; ks++) {
            uint32_t af[4][4], bf[4][2];
#pragma unroll
            for (int mt = 0; mt < 4; mt++) {
                int mb = wm + mt * 16;
                af[mt][0] = As[(mb + g) * LDA + ks * 8 + tg];
                af[mt][1] = As[(mb + g + 8) * LDA + ks * 8 + tg];
                af[mt][2] = As[(mb + g) * LDA + ks * 8 + tg + 4];
                af[mt][3] = As[(mb + g + 8) * LDA + ks * 8 + tg + 4];
            }
#pragma unroll
            for (int nt = 0; nt < 4; nt++) {
                int col = wn + nt * 8 + g;
                bf[nt][0] = Bs[(ks * 8 + tg) * LDB + col];
                bf[nt][1] = Bs[(ks * 8 + tg + 4) * LDB + col];
            }
#pragma unroll
            for (int mt = 0; mt < 4; mt++)
#pragma unroll
                for (int nt = 0; nt < 4; nt++)
                    mma_tf32(acc[mt][nt], af[mt], bf[nt]);
        }
        __syncthreads();
    }

    const float scale = 0.125f;
#pragma unroll
    for (int mt = 0; mt < 4; mt++) {
        int r0 = m0 + wm + mt * 16 + g;
#pragma unroll
        for (int nt = 0; nt < 4; nt++) {
            int col = n0 + wn + nt * 8 + 2 * tg;
            int mk0 = mask[b * SEQ + col], mk1 = mask[b * SEQ + col + 1];
            float v0 = acc[mt][nt][0] * scale, v1 = acc[mt][nt][1] * scale;
            float v2 = acc[mt][nt][2] * scale, v3 = acc[mt][nt][3] * scale;
            if (mk0 == 0) { v0 = -1e9f; v2 = -1e9f; }
            if (mk1 == 0) { v1 = -1e9f; v3 = -1e9f; }
            *(float2*)&attn[((size_t)bh * SEQ + r0) * SEQ + col] = make_float2(v0, v1);
            *(float2*)&attn[((size_t)bh * SEQ + r0 + 8) * SEQ + col] = make_float2(v2, v3);
        }
    }
}

// ---------------------------------------------------------------------------
// Row softmax over 2048 elems, float4-vectorized, shuffle reductions
// ---------------------------------------------------------------------------
__global__ void __launch_bounds__(256) softmax_k(float* __restrict__ attn)
{
    float4* p = (float4*)(attn + (size_t)blockIdx.x * SEQ);
    const int tid = threadIdx.x, lane = tid & 31, wid = tid >> 5;
    __shared__ float red[8];
    float4 v0 = p[tid], v1 = p[tid + 256];

    float mx = fmaxf(fmaxf(fmaxf(v0.x, v0.y), fmaxf(v0.z, v0.w)),
                     fmaxf(fmaxf(v1.x, v1.y), fmaxf(v1.z, v1.w)));
#pragma unroll
    for (int s = 16; s > 0; s >>= 1) mx = fmaxf(mx, __shfl_xor_sync(0xffffffff, mx, s));
    if (lane == 0) red[wid] = mx;
    __syncthreads();
    mx = red[0];
#pragma unroll
    for (int i = 1; i < 8; i++) mx = fmaxf(mx, red[i]);
    __syncthreads();

    v0.x = __expf(v0.x - mx); v0.y = __expf(v0.y - mx);
    v0.z = __expf(v0.z - mx); v0.w = __expf(v0.w - mx);
    v1.x = __expf(v1.x - mx); v1.y = __expf(v1.y - mx);
    v1.z = __expf(v1.z - mx); v1.w = __expf(v1.w - mx);
    float sum = v0.x + v0.y + v0.z + v0.w + v1.x + v1.y + v1.z + v1.w;
#pragma unroll
    for (int s = 16; s > 0; s >>= 1) sum += __shfl_xor_sync(0xffffffff, sum, s);
    if (lane == 0) red[wid] = sum;
    __syncthreads();
    sum = red[0];
#pragma unroll
    for (int i = 1; i < 8; i++) sum += red[i];
    float inv = 1.0f / sum;

    v0.x *= inv; v0.y *= inv; v0.z *= inv; v0.w *= inv;
    v1.x *= inv; v1.y *= inv; v1.z *= inv; v1.w *= inv;
    p[tid] = v0;
    p[tid + 256] = v1;
}

// ---------------------------------------------------------------------------
// ctx = attn @ V_h (tf32): per (b,h) M=2048 N=64 K=2048; BM=128 BN=64 BK=32
// 8 warps, warp tile 32x32 (mtiles=2, ntiles=4)
// ---------------------------------------------------------------------------
__global__ void __launch_bounds__(256) av_tf32_k(const float* __restrict__ attn)
{
    constexpr int BM = 128, BN = 64, BK = 32, LDA = BK + 4, LDB = BN + 8;
    __shared__ uint32_t As[BM * LDA];
    __shared__ uint32_t Bs[BK * LDB];
    const int bh = blockIdx.y, b = bh >> 4, h = bh & 15;
    const int m0 = blockIdx.x * BM;
    const float* arow = attn + ((size_t)bh * SEQ + m0) * SEQ;
    const float* vb = g_V + (size_t)b * SEQ * DMODEL + h * DK;
    const int tid = threadIdx.x, lane = tid & 31, wid = tid >> 5;
    const int wm = (wid & 3) * 32, wn = (wid >> 2) * 32;
    const int g = lane >> 2, tg = lane & 3;
    const int aRow = tid >> 3, aCol = (tid & 7) * 4;
    const int vRow = tid >> 4, vCol = (tid & 15) * 4;

    float4 pa[4], pb[2];
#pragma unroll
    for (int r = 0; r < 4; r++)
        pa[r] = *(const float4*)&arow[(size_t)(aRow + r * 32) * SEQ + aCol];
#pragma unroll
    for (int r = 0; r < 2; r++)
        pb[r] = *(const float4*)&vb[(size_t)(vRow + r * 16) * DMODEL + vCol];

    float acc[2][4][4] = {};

    for (int k0 = 0; k0 < SEQ; k0 += BK) {
#pragma unroll
        for (int r = 0; r < 4; r++) {
            uint4 va = {f2tf(pa[r].x), f2tf(pa[r].y), f2tf(pa[r].z), f2tf(pa[r].w)};
            *(uint4*)&As[(aRow + r * 32) * LDA + aCol] = va;
        }
#pragma unroll
        for (int r = 0; r < 2; r++) {
            uint4 vv = {f2tf(pb[r].x), f2tf(pb[r].y), f2tf(pb[r].z), f2tf(pb[r].w)};
            *(uint4*)&Bs[(vRow + r * 16) * LDB + vCol] = vv;
        }
        __syncthreads();
        if (k0 + BK < SEQ) {
#pragma unroll
            for (int r = 0; r < 4; r++)
                pa[r] = *(const float4*)&arow[(size_t)(aRow + r * 32) * SEQ + k0 + BK + aCol];
#pragma unroll
            for (int r = 0; r < 2; r++)
                pb[r] = *(const float4*)&vb[(size_t)(k0 + BK + vRow + r * 16) * DMODEL + vCol];
        }
#pragma unroll
        for (int ks = 0; ks < 4; ks++) {
            uint32_t af[2][4], bf[4][2];
#pragma unroll
            for (int mt = 0; mt < 2; mt++) {
                int mb = wm + mt * 16;
                af[mt][0] = As[(mb + g) * LDA + ks * 8 + tg];
                af[mt][1] = As[(mb + g + 8) * LDA + ks * 8 + tg];
                af[mt][2] = As[(mb + g) * LDA + ks * 8 + tg + 4];
                af[mt][3] = As[(mb + g + 8) * LDA + ks * 8 + tg + 4];
            }
#pragma unroll
            for (int nt = 0; nt < 4; nt++) {
                int col = wn + nt * 8 + g;
                bf[nt][0] = Bs[(ks * 8 + tg) * LDB + col];
                bf[nt][1] = Bs[(ks * 8 + tg + 4) * LDB + col];
            }
#pragma unroll
            for (int mt = 0; mt < 2; mt++)
#pragma unroll
                for (int nt = 0; nt < 4; nt++)
                    mma_tf32(acc[mt][nt], af[mt], bf[nt]);
        }
        __syncthreads();
    }

#pragma unroll
    for (int mt = 0; mt < 2; mt++) {
        int r0 = m0 + wm + mt * 16 + g;
#pragma unroll
        for (int nt = 0; nt < 4; nt++) {
            int col = wn + nt * 8 + 2 * tg;
            *(float2*)&g_ctx[(size_t)(b * SEQ + r0) * DMODEL + h * DK + col] =
                make_float2(acc[mt][nt][0], acc[mt][nt][1]);
            *(float2*)&g_ctx[(size_t)(b * SEQ + r0 + 8) * DMODEL + h * DK + col] =
                make_float2(acc[mt][nt][2], acc[mt][nt][3]);
        }
    }
}

// ---------------------------------------------------------------------------
extern "C" void kernel_launch(void* const* d_in, const int* in_sizes, int n_in,
                              void* d_out, int out_size)
{
    const float* query = (const float*)d_in[0];
    const float* key_i = (const float*)d_in[1];
    const float* value = (const float*)d_in[2];
    const int*   mask  = (const int*)d_in[3];
    const float* w_q = (const float*)d_in[4];
    const float* b_q = (const float*)d_in[5];
    const float* w_k = (const float*)d_in[6];
    const float* b_k = (const float*)d_in[7];
    const float* w_v = (const float*)d_in[8];
    const float* b_v = (const float*)d_in[9];
    const float* w_o = (const float*)d_in[10];
    const float* b_o = (const float*)d_in[11];

    float *pQ, *pK, *pV, *pCtx, *pWt, *pAttn, *pOutS;
    cudaGetSymbolAddress((void**)&pQ, g_Q);
    cudaGetSymbolAddress((void**)&pK, g_K);
    cudaGetSymbolAddress((void**)&pV, g_V);
    cudaGetSymbolAddress((void**)&pCtx, g_ctx);
    cudaGetSymbolAddress((void**)&pWt, g_Wt);
    cudaGetSymbolAddress((void**)&pAttn, g_attn);
    cudaGetSymbolAddress((void**)&pOutS, g_outscratch);

    float* outp = (float*)d_out;
    float* attnp;
    long long osz = (long long)out_size;
    if (osz >= OUT_ELEMS + ATTN_ELEMS) {
        attnp = (float*)d_out + OUT_ELEMS;
    } else if (osz == ATTN_ELEMS) {
        attnp = (float*)d_out;
        outp = pOutS;
    } else {
        attnp = pAttn;
    }

    const int W = DMODEL * DMODEL;
    dim3 tb(32, 8);
    transpose_k<<<dim3(32, 32), tb>>>(w_q, pWt + 0 * W);
    transpose_k<<<dim3(32, 32), tb>>>(w_k, pWt + 1 * W);
    transpose_k<<<dim3(32, 32), tb>>>(w_v, pWt + 2 * W);
    transpose_k<<<dim3(32, 32), tb>>>(w_o, pWt + 3 * W);

    sgemm_tf32_k<<<dim3(8, 32), 256>>>(query, pWt + 0 * W, b_q, pQ);
    sgemm_tf32_k<<<dim3(8, 32), 256>>>(key_i, pWt + 1 * W, b_k, pK);
    sgemm_tf32_k<<<dim3(8, 32), 256>>>(value, pWt + 2 * W, b_v, pV);

    scores_tf32_k<<<dim3(16, 16, BATCH * NHEAD), 256>>>(attnp, mask);
    softmax_k<<<dim3(BATCH * NHEAD * SEQ), 256>>>(attnp);
    av_tf32_k<<<dim3(16, BATCH * NHEAD), 256>>>(attnp);

    sgemm_tf32_k<<<dim3(8, 32), 256>>>(pCtx, pWt + 3 * W, b_o, outp);
}